// round 1
// baseline (speedup 1.0000x reference)
#include <cuda_runtime.h>
#include <cuda_bf16.h>

#define N_IMG   8
#define N_ANCH  250000
#define PRE_K   2000
#define POST_K  1000
#define NBINS   8192        // 13-bit monotone-float histogram
#define CAND_MAX 4096
#define COLB    32          // ceil(2000/64)
#define NMS_TH  0.7f
#define BBOX_CLIP 4.135166556742356f

// -------- persistent device scratch (no allocs allowed) --------
__device__ unsigned int       g_hist[N_IMG][NBINS];
__device__ unsigned int       g_thresh[N_IMG];
__device__ unsigned int       g_cnt[N_IMG];
__device__ unsigned long long g_cand[N_IMG][CAND_MAX];
__device__ float4             g_box[N_IMG][PRE_K];
__device__ float              g_score[N_IMG][PRE_K];
__device__ unsigned char      g_valid[N_IMG][PRE_K];
__device__ unsigned long long g_mask[N_IMG][PRE_K][COLB];
__device__ int                g_rowAny[N_IMG][PRE_K];

__device__ __forceinline__ unsigned int monof(float f) {
    unsigned int u = __float_as_uint(f);
    return (u & 0x80000000u) ? ~u : (u | 0x80000000u);
}

// -------- stage 1: histogram over top 13 bits of monotone key --------
__global__ void k_hist(const float* __restrict__ obj) {
    int img = blockIdx.y;
    int i = blockIdx.x * blockDim.x + threadIdx.x;
    if (i < N_ANCH) {
        unsigned int m = monof(obj[img * N_ANCH + i]) >> 19;
        atomicAdd(&g_hist[img][m], 1u);
    }
}

// -------- stage 2: per-image threshold bin (descending cumulative >= PRE_K) --------
__global__ void k_thresh() {
    __shared__ unsigned int part[1024];
    int img = blockIdx.x;
    int t = threadIdx.x;
    unsigned int s = 0;
    int base = NBINS - 1 - t * 8;            // group t covers 8 bins, descending
    #pragma unroll
    for (int m = 0; m < 8; m++) s += g_hist[img][base - m];
    part[t] = s;
    __syncthreads();
    if (t == 0) {
        unsigned int cum = 0;
        int g = 1023;
        for (int q = 0; q < 1024; q++) {
            if (cum + part[q] >= PRE_K) { g = q; break; }
            cum += part[q];
        }
        int bb = NBINS - 1 - g * 8;
        unsigned int th = 0;
        for (int m = 0; m < 8; m++) {
            cum += g_hist[img][bb - m];
            if (cum >= PRE_K) { th = (unsigned int)(bb - m); break; }
        }
        g_thresh[img] = th;
    }
}

// -------- stage 3: gather all candidates in bins >= threshold --------
__global__ void k_gather(const float* __restrict__ obj) {
    int img = blockIdx.y;
    int i = blockIdx.x * blockDim.x + threadIdx.x;
    if (i >= N_ANCH) return;
    unsigned int m = monof(obj[img * N_ANCH + i]);
    if ((m >> 19) >= g_thresh[img]) {
        unsigned int p = atomicAdd(&g_cnt[img], 1u);
        if (p < CAND_MAX)
            g_cand[img][p] = ((unsigned long long)m << 32) | (unsigned int)(~(unsigned int)i);
    }
}

// -------- stage 4: exact bitonic sort of candidates + box decode/clip --------
__global__ void k_sortdecode(const float4* __restrict__ anchors,
                             const float4* __restrict__ deltas) {
    __shared__ unsigned long long s[CAND_MAX];   // 32 KB
    int img = blockIdx.x;
    int tid = threadIdx.x;
    unsigned int cnt = g_cnt[img];
    int n = (cnt < CAND_MAX) ? (int)cnt : CAND_MAX;
    for (int i = tid; i < CAND_MAX; i += blockDim.x)
        s[i] = (i < n) ? g_cand[img][i] : 0ull;
    __syncthreads();

    // bitonic, descending (key = mono<<32 | ~idx  => score desc, idx asc)
    for (int k = 2; k <= CAND_MAX; k <<= 1) {
        for (int j = k >> 1; j > 0; j >>= 1) {
            for (int i = tid; i < CAND_MAX; i += blockDim.x) {
                int ixj = i ^ j;
                if (ixj > i) {
                    unsigned long long a = s[i], b = s[ixj];
                    bool descSeg = (i & k) == 0;
                    if (descSeg ? (a < b) : (a > b)) { s[i] = b; s[ixj] = a; }
                }
            }
            __syncthreads();
        }
    }

    for (int t = tid; t < PRE_K; t += blockDim.x) {
        unsigned long long key = s[t];
        unsigned int idx = ~(unsigned int)(key & 0xFFFFFFFFull);
        unsigned int m = (unsigned int)(key >> 32);
        float score = __uint_as_float((m & 0x80000000u) ? (m ^ 0x80000000u) : ~m);
        float4 a = anchors[idx];
        float4 d = deltas[(size_t)img * N_ANCH + idx];
        float w = a.z - a.x + 1.0f, h = a.w - a.y + 1.0f;
        float cx = a.x + 0.5f * w, cy = a.y + 0.5f * h;
        float dw = fminf(d.z, BBOX_CLIP), dh = fminf(d.w, BBOX_CLIP);
        float pcx = d.x * w + cx, pcy = d.y * h + cy;
        float pw = expf(dw) * w, ph = expf(dh) * h;
        float x1 = pcx - 0.5f * pw, y1 = pcy - 0.5f * ph;
        float x2 = pcx + 0.5f * pw - 1.0f, y2 = pcy + 0.5f * ph - 1.0f;
        x1 = fminf(fmaxf(x1, 0.0f), 1332.0f);
        y1 = fminf(fmaxf(y1, 0.0f), 799.0f);
        x2 = fminf(fmaxf(x2, 0.0f), 1332.0f);
        y2 = fminf(fmaxf(y2, 0.0f), 799.0f);
        g_box[img][t] = make_float4(x1, y1, x2, y2);
        g_score[img][t] = score;
        g_valid[img][t] = ((x2 - x1 + 1.0f) >= 0.0f && (y2 - y1 + 1.0f) >= 0.0f) ? 1 : 0;
    }
}

// -------- stage 5: pairwise IoU suppression bitmask (upper triangle) --------
__global__ void k_mask() {
    int colB = blockIdx.x, rowB = blockIdx.y, img = blockIdx.z;
    if (colB < rowB) return;
    __shared__ float4 cb[64];
    __shared__ float  ca[64];
    int t = threadIdx.x;
    int col0 = colB * 64;
    if (col0 + t < PRE_K) {
        float4 b = g_box[img][col0 + t];
        cb[t] = b;
        ca[t] = (b.z - b.x + 1.0f) * (b.w - b.y + 1.0f);
    }
    __syncthreads();
    int row = rowB * 64 + t;
    if (row >= PRE_K) return;
    float4 rb = g_box[img][row];
    float ra = (rb.z - rb.x + 1.0f) * (rb.w - rb.y + 1.0f);
    unsigned long long bits = 0;
    int cmax = min(64, PRE_K - col0);
    for (int c = 0; c < cmax; c++) {
        int col = col0 + c;
        if (col <= row) continue;
        float4 b = cb[c];
        float lx = fmaxf(rb.x, b.x), ly = fmaxf(rb.y, b.y);
        float rx = fminf(rb.z, b.z), ry = fminf(rb.w, b.w);
        float iw = fmaxf(rx - lx + 1.0f, 0.0f);
        float ih = fmaxf(ry - ly + 1.0f, 0.0f);
        float inter = iw * ih;
        if (inter > NMS_TH * (ra + ca[c] - inter)) bits |= 1ull << c;
    }
    g_mask[img][row][colB] = bits;
    if (bits) g_rowAny[img][row] = 1;
}

// -------- stage 6: greedy NMS reduce (warp 0) + stable partition + output --------
__global__ void k_nms_out(float* __restrict__ out) {
    int img = blockIdx.x;
    __shared__ unsigned long long sKeep[COLB];
    __shared__ int wordPre[COLB + 1];
    int tid = threadIdx.x;

    if (tid < 32) {
        int j = tid;
        unsigned long long remv = 0;
        for (int b = 0; b < COLB; b++) {
            unsigned long long cur = __shfl_sync(0xffffffffu, remv, b);
            unsigned long long kept = 0;
            if (j == b) {
                int r0 = b * 64;
                int rmax = min(64, PRE_K - r0);
                unsigned long long diag[64];
                for (int i2 = 0; i2 < 64; i2++)
                    diag[i2] = (i2 < rmax) ? g_mask[img][r0 + i2][b] : 0ull;
                unsigned char vl[64];
                for (int i2 = 0; i2 < 64; i2++)
                    vl[i2] = (i2 < rmax) ? g_valid[img][r0 + i2] : 0;
                for (int i2 = 0; i2 < rmax; i2++) {
                    if (vl[i2] && !((cur >> i2) & 1ull)) {
                        kept |= 1ull << i2;
                        cur |= diag[i2];
                    }
                }
                remv = cur;
                sKeep[b] = kept;
            }
            kept = __shfl_sync(0xffffffffu, kept, b);
            if (j > b) {
                unsigned long long kk = kept;
                while (kk) {
                    int bit = __ffsll((long long)kk) - 1;
                    kk &= kk - 1;
                    int row = b * 64 + bit;
                    if (g_rowAny[img][row]) remv |= g_mask[img][row][j];
                }
            }
        }
        __syncwarp();
        wordPre[j] = __popcll(sKeep[j]);
        __syncwarp();
        if (j == 0) {
            int c = 0;
            for (int q = 0; q < COLB; q++) { int v = wordPre[q]; wordPre[q] = c; c += v; }
            wordPre[COLB] = c;
        }
    }
    __syncthreads();

    int nk = wordPre[COLB];
    for (int i = tid; i < PRE_K; i += blockDim.x) {
        int w = i >> 6, bit = i & 63;
        unsigned long long kw = sKeep[w];
        int before = wordPre[w] + __popcll(kw & ((1ull << bit) - 1ull));
        bool kept = (kw >> bit) & 1ull;
        int pos = kept ? before : nk + (i - before);
        if (pos < POST_K) {
            float4 bx = g_box[img][i];
            float sc = kept ? g_score[img][i] : -1e9f;
            float* o = out + ((size_t)img * POST_K + pos) * 5;
            o[0] = bx.x; o[1] = bx.y; o[2] = bx.z; o[3] = bx.w; o[4] = sc;
        }
    }
}

extern "C" void kernel_launch(void* const* d_in, const int* in_sizes, int n_in,
                              void* d_out, int out_size) {
    const float* anchors = (const float*)d_in[0];   // [250000,4]
    const float* obj     = (const float*)d_in[1];   // [8,250000]
    const float* deltas  = (const float*)d_in[2];   // [8,250000,4]
    float* out = (float*)d_out;                     // [8,1000,5]
    (void)in_sizes; (void)n_in; (void)out_size;

    void *hp, *cp, *rp;
    cudaGetSymbolAddress(&hp, g_hist);
    cudaGetSymbolAddress(&cp, g_cnt);
    cudaGetSymbolAddress(&rp, g_rowAny);
    cudaMemsetAsync(hp, 0, sizeof(unsigned int) * N_IMG * NBINS, 0);
    cudaMemsetAsync(cp, 0, sizeof(unsigned int) * N_IMG, 0);
    cudaMemsetAsync(rp, 0, sizeof(int) * N_IMG * PRE_K, 0);

    dim3 gh((N_ANCH + 255) / 256, N_IMG);
    k_hist<<<gh, 256>>>(obj);
    k_thresh<<<N_IMG, 1024>>>();
    k_gather<<<gh, 256>>>(obj);
    k_sortdecode<<<N_IMG, 1024>>>((const float4*)anchors, (const float4*)deltas);
    k_mask<<<dim3(COLB, COLB, N_IMG), 64>>>();
    k_nms_out<<<N_IMG, 1024>>>(out);
}

// round 2
// speedup vs baseline: 2.2008x; 2.2008x over previous
#include <cuda_runtime.h>
#include <cuda_bf16.h>

#define N_IMG   8
#define N_ANCH  250000
#define PRE_K   2000
#define POST_K  1000
#define NBINS   131072      // 17-bit monotone-float histogram
#define CAND_MAX 4096
#define LIST_MAX 2048
#define NMS_TH  0.7f
#define BBOX_CLIP 4.135166556742356f

// -------- persistent device scratch (no allocs allowed) --------
__device__ unsigned int       g_hist[N_IMG][NBINS];     // 4 MB
__device__ unsigned int       g_thresh[N_IMG];
__device__ unsigned int       g_cnt[N_IMG];
__device__ unsigned long long g_cand[N_IMG][CAND_MAX];
__device__ float4             g_box[N_IMG][PRE_K];
__device__ float              g_score[N_IMG][PRE_K];
__device__ unsigned char      g_valid[N_IMG][PRE_K];
__device__ unsigned int       g_cnt2[N_IMG];
__device__ int                g_lkey[N_IMG][LIST_MAX];
__device__ unsigned long long g_lword[N_IMG][LIST_MAX];

__device__ __forceinline__ unsigned int monof(float f) {
    unsigned int u = __float_as_uint(f);
    return (u & 0x80000000u) ? ~u : (u | 0x80000000u);
}

// -------- stage 1: histogram over top 17 bits of monotone key --------
__global__ void k_hist(const float* __restrict__ obj) {
    int img = blockIdx.y;
    int i = blockIdx.x * blockDim.x + threadIdx.x;
    if (i < N_ANCH) {
        unsigned int m = monof(obj[img * N_ANCH + i]) >> 15;
        atomicAdd(&g_hist[img][m], 1u);
    }
}

// -------- stage 2: per-image threshold bin (parallel descending cumulative) --------
__global__ void k_thresh() {
    __shared__ unsigned int ps[1024];
    __shared__ unsigned int fb[128];
    __shared__ int gsel;
    __shared__ unsigned int exclv;
    int img = blockIdx.x, t = threadIdx.x;
    ps[t] = 0;
    __syncthreads();
    // coalesced hist read, transpose into descending group sums via shared atomics
    const uint4* h4 = (const uint4*)g_hist[img];
    #pragma unroll
    for (int k2 = 0; k2 < 32; k2++) {
        int q = t + k2 * 1024;          // uint4 index, 32768 total
        uint4 v = h4[q];
        int grp = 1023 - ((q * 4) >> 7);  // 128 bins per group, group 0 = top bins
        unsigned int s = v.x + v.y + v.z + v.w;
        if (s) atomicAdd(&ps[grp], s);
    }
    __syncthreads();
    // inclusive Hillis-Steele scan over 1024 group sums
    for (int off = 1; off < 1024; off <<= 1) {
        unsigned int v = (t >= off) ? ps[t - off] : 0u;
        __syncthreads();
        ps[t] += v;
        __syncthreads();
    }
    if (ps[t] >= PRE_K && (t == 0 || ps[t - 1] < PRE_K)) {
        gsel = t;
        exclv = (t == 0) ? 0u : ps[t - 1];
    }
    __syncthreads();
    int g = gsel;
    int binHi = (1023 - g) * 128 + 127;
    if (t < 128) fb[t] = g_hist[img][binHi - t];   // descending within group
    __syncthreads();
    if (t == 0) {
        unsigned int cum = exclv;
        unsigned int th = 0;
        for (int m = 0; m < 128; m++) {
            cum += fb[m];
            if (cum >= PRE_K) { th = (unsigned int)(binHi - m); break; }
        }
        g_thresh[img] = th;
    }
}

// -------- stage 3: gather all candidates in bins >= threshold --------
__global__ void k_gather(const float* __restrict__ obj) {
    int img = blockIdx.y;
    int i = blockIdx.x * blockDim.x + threadIdx.x;
    if (i >= N_ANCH) return;
    unsigned int m = monof(obj[img * N_ANCH + i]);
    if ((m >> 15) >= g_thresh[img]) {
        unsigned int p = atomicAdd(&g_cnt[img], 1u);
        if (p < CAND_MAX)
            g_cand[img][p] = ((unsigned long long)m << 32) | (unsigned int)(~(unsigned int)i);
    }
}

// -------- stage 4: exact bitonic sort (dynamic 2048/4096) + box decode/clip --------
__global__ void k_sortdecode(const float4* __restrict__ anchors,
                             const float4* __restrict__ deltas) {
    __shared__ unsigned long long s[CAND_MAX];   // 32 KB
    int img = blockIdx.x;
    int tid = threadIdx.x;
    unsigned int cnt = g_cnt[img];
    int n = (cnt < CAND_MAX) ? (int)cnt : CAND_MAX;
    int S = (n <= 2048) ? 2048 : 4096;
    for (int i = tid; i < S; i += blockDim.x)
        s[i] = (i < n) ? g_cand[img][i] : 0ull;
    __syncthreads();

    // bitonic, descending (key = mono<<32 | ~idx  => score desc, idx asc)
    for (int k = 2; k <= S; k <<= 1) {
        for (int j = k >> 1; j > 0; j >>= 1) {
            for (int i = tid; i < S; i += blockDim.x) {
                int ixj = i ^ j;
                if (ixj > i) {
                    unsigned long long a = s[i], b = s[ixj];
                    bool descSeg = (i & k) == 0;
                    if (descSeg ? (a < b) : (a > b)) { s[i] = b; s[ixj] = a; }
                }
            }
            __syncthreads();
        }
    }

    for (int t = tid; t < PRE_K; t += blockDim.x) {
        unsigned long long key = s[t];
        unsigned int idx = ~(unsigned int)(key & 0xFFFFFFFFull);
        unsigned int m = (unsigned int)(key >> 32);
        float score = __uint_as_float((m & 0x80000000u) ? (m ^ 0x80000000u) : ~m);
        float4 a = anchors[idx];
        float4 d = deltas[(size_t)img * N_ANCH + idx];
        float w = a.z - a.x + 1.0f, h = a.w - a.y + 1.0f;
        float cx = a.x + 0.5f * w, cy = a.y + 0.5f * h;
        float dw = fminf(d.z, BBOX_CLIP), dh = fminf(d.w, BBOX_CLIP);
        float pcx = d.x * w + cx, pcy = d.y * h + cy;
        float pw = expf(dw) * w, ph = expf(dh) * h;
        float x1 = pcx - 0.5f * pw, y1 = pcy - 0.5f * ph;
        float x2 = pcx + 0.5f * pw - 1.0f, y2 = pcy + 0.5f * ph - 1.0f;
        x1 = fminf(fmaxf(x1, 0.0f), 1332.0f);
        y1 = fminf(fmaxf(y1, 0.0f), 799.0f);
        x2 = fminf(fmaxf(x2, 0.0f), 1332.0f);
        y2 = fminf(fmaxf(y2, 0.0f), 799.0f);
        g_box[img][t] = make_float4(x1, y1, x2, y2);
        g_score[img][t] = score;
        g_valid[img][t] = ((x2 - x1 + 1.0f) >= 0.0f && (y2 - y1 + 1.0f) >= 0.0f) ? 1 : 0;
    }
}

// -------- stage 5: IoU suppression, sparse nonzero-word list append --------
__global__ void k_mask() {
    int colB = blockIdx.x, rowB = blockIdx.y, img = blockIdx.z;
    if (colB < rowB) return;
    __shared__ float4 cb[64];
    __shared__ float  ca[64];
    int t = threadIdx.x;
    int col0 = colB * 64;
    if (col0 + t < PRE_K) {
        float4 b = g_box[img][col0 + t];
        cb[t] = b;
        ca[t] = (b.z - b.x + 1.0f) * (b.w - b.y + 1.0f);
    }
    __syncthreads();
    int row = rowB * 64 + t;
    if (row >= PRE_K) return;
    float4 rb = g_box[img][row];
    float ra = (rb.z - rb.x + 1.0f) * (rb.w - rb.y + 1.0f);
    unsigned long long bits = 0;
    int cmax = min(64, PRE_K - col0);
    for (int c = 0; c < cmax; c++) {
        int col = col0 + c;
        if (col <= row) continue;
        float4 b = cb[c];
        float lx = fmaxf(rb.x, b.x), ly = fmaxf(rb.y, b.y);
        float rx = fminf(rb.z, b.z), ry = fminf(rb.w, b.w);
        float iw = fmaxf(rx - lx + 1.0f, 0.0f);
        float ih = fmaxf(ry - ly + 1.0f, 0.0f);
        float inter = iw * ih;
        if (inter > NMS_TH * (ra + ca[c] - inter)) bits |= 1ull << c;
    }
    if (bits) {
        unsigned int p = atomicAdd(&g_cnt2[img], 1u);
        if (p < LIST_MAX) {
            g_lkey[img][p] = (row << 5) | colB;
            g_lword[img][p] = bits;
        }
    }
}

// -------- stage 6: sparse greedy NMS + stable partition + output --------
__global__ void k_nms_out(float* __restrict__ out) {
    int img = blockIdx.x, tid = threadIdx.x;
    __shared__ unsigned int       v32[64];
    __shared__ unsigned long long rem64[32];
    __shared__ unsigned long long keep64s[32];
    __shared__ int                skey[LIST_MAX];
    __shared__ unsigned long long sword[LIST_MAX];
    __shared__ int                wordPre[33];

    if (tid < 64) v32[tid] = 0;
    if (tid < 32) rem64[tid] = 0;
    __syncthreads();

    // validity bits via ballot (rows 0..1999)
    {
        int i = tid;
        unsigned char vv = (i < PRE_K) ? g_valid[img][i] : 0;
        unsigned int b = __ballot_sync(0xffffffffu, vv != 0);
        if ((tid & 31) == 0) v32[tid >> 5] = b;
        i = tid + 1024;
        vv = (i < PRE_K) ? g_valid[img][i] : 0;
        b = __ballot_sync(0xffffffffu, vv != 0);
        if ((tid & 31) == 0) v32[32 + (tid >> 5)] = b;
    }
    unsigned int c2 = g_cnt2[img];
    int n = (c2 < LIST_MAX) ? (int)c2 : LIST_MAX;
    for (int e = tid; e < n; e += 1024) {
        skey[e] = g_lkey[img][e];
        sword[e] = g_lword[img][e];
    }
    __syncthreads();

    if (tid == 0) {
        // insertion sort by (row,colB) key — n expected ~tens
        for (int a = 1; a < n; a++) {
            int k = skey[a];
            unsigned long long w = sword[a];
            int b = a - 1;
            while (b >= 0 && skey[b] > k) {
                skey[b + 1] = skey[b];
                sword[b + 1] = sword[b];
                b--;
            }
            skey[b + 1] = k;
            sword[b + 1] = w;
        }
        // exact greedy over sparse entries, rows ascending
        int e = 0;
        while (e < n) {
            int r = skey[e] >> 5;
            bool kp = ((v32[r >> 5] >> (r & 31)) & 1u) &&
                      !((rem64[r >> 6] >> (r & 63)) & 1ull);
            if (kp) {
                do { rem64[skey[e] & 31] |= sword[e]; e++; }
                while (e < n && (skey[e] >> 5) == r);
            } else {
                do { e++; } while (e < n && (skey[e] >> 5) == r);
            }
        }
    }
    __syncthreads();

    if (tid < 32) {
        unsigned long long vd = ((unsigned long long)v32[2 * tid]) |
                                (((unsigned long long)v32[2 * tid + 1]) << 32);
        unsigned long long kw = vd & ~rem64[tid];
        keep64s[tid] = kw;
        wordPre[tid] = __popcll(kw);
    }
    __syncthreads();
    if (tid == 0) {
        int c = 0;
        for (int q = 0; q < 32; q++) { int v = wordPre[q]; wordPre[q] = c; c += v; }
        wordPre[32] = c;
    }
    __syncthreads();

    int nk = wordPre[32];
    for (int i = tid; i < PRE_K; i += 1024) {
        int w = i >> 6, bit = i & 63;
        unsigned long long kw = keep64s[w];
        int before = wordPre[w] + __popcll(kw & ((1ull << bit) - 1ull));
        bool kept = (kw >> bit) & 1ull;
        int pos = kept ? before : nk + (i - before);
        if (pos < POST_K) {
            float4 bx = g_box[img][i];
            float sc = kept ? g_score[img][i] : -1e9f;
            float* o = out + ((size_t)img * POST_K + pos) * 5;
            o[0] = bx.x; o[1] = bx.y; o[2] = bx.z; o[3] = bx.w; o[4] = sc;
        }
    }
}

extern "C" void kernel_launch(void* const* d_in, const int* in_sizes, int n_in,
                              void* d_out, int out_size) {
    const float* anchors = (const float*)d_in[0];   // [250000,4]
    const float* obj     = (const float*)d_in[1];   // [8,250000]
    const float* deltas  = (const float*)d_in[2];   // [8,250000,4]
    float* out = (float*)d_out;                     // [8,1000,5]
    (void)in_sizes; (void)n_in; (void)out_size;

    void *hp, *cp, *c2p;
    cudaGetSymbolAddress(&hp, g_hist);
    cudaGetSymbolAddress(&cp, g_cnt);
    cudaGetSymbolAddress(&c2p, g_cnt2);
    cudaMemsetAsync(hp, 0, sizeof(unsigned int) * N_IMG * NBINS, 0);
    cudaMemsetAsync(cp, 0, sizeof(unsigned int) * N_IMG, 0);
    cudaMemsetAsync(c2p, 0, sizeof(unsigned int) * N_IMG, 0);

    dim3 gh((N_ANCH + 255) / 256, N_IMG);
    k_hist<<<gh, 256>>>(obj);
    k_thresh<<<N_IMG, 1024>>>();
    k_gather<<<gh, 256>>>(obj);
    k_sortdecode<<<N_IMG, 1024>>>((const float4*)anchors, (const float4*)deltas);
    k_mask<<<dim3(32, 32, N_IMG), 64>>>();
    k_nms_out<<<N_IMG, 1024>>>(out);
}

// round 5
// speedup vs baseline: 4.8503x; 2.2039x over previous
#include <cuda_runtime.h>
#include <cuda_bf16.h>

#define N_IMG   8
#define N_ANCH  250000      // divisible by 4 -> 62500 float4 per image
#define N_ANCH4 62500
#define PRE_K   2000
#define POST_K  1000
#define NBINS   131072      // 17-bit monotone-float histogram
#define CAND_MAX 4096
#define LIST_MAX 2048
#define NMS_TH  0.7f
#define BBOX_CLIP 4.135166556742356f

// -------- persistent device scratch (no allocs allowed) --------
__device__ unsigned int       g_hist[N_IMG][NBINS];     // 4 MB
__device__ unsigned int       g_thresh[N_IMG];
__device__ unsigned int       g_cnt[N_IMG];
__device__ unsigned long long g_cand[N_IMG][CAND_MAX];
__device__ float4             g_box[N_IMG][PRE_K];
__device__ float              g_score[N_IMG][PRE_K];
__device__ unsigned char      g_valid[N_IMG][PRE_K];
__device__ unsigned int       g_cnt2[N_IMG];
__device__ int                g_lkey[N_IMG][LIST_MAX];
__device__ unsigned long long g_lword[N_IMG][LIST_MAX];

__device__ __forceinline__ unsigned int monof(float f) {
    unsigned int u = __float_as_uint(f);
    return (u & 0x80000000u) ? ~u : (u | 0x80000000u);
}

// -------- stage 1: histogram over top 17 bits of monotone key (float4) --------
__global__ void k_hist(const float4* __restrict__ obj4) {
    int img = blockIdx.y;
    int i = blockIdx.x * blockDim.x + threadIdx.x;
    if (i < N_ANCH4) {
        float4 v = obj4[(size_t)img * N_ANCH4 + i];
        atomicAdd(&g_hist[img][monof(v.x) >> 15], 1u);
        atomicAdd(&g_hist[img][monof(v.y) >> 15], 1u);
        atomicAdd(&g_hist[img][monof(v.z) >> 15], 1u);
        atomicAdd(&g_hist[img][monof(v.w) >> 15], 1u);
    }
}

// -------- stage 2: per-image threshold bin (parallel descending cumulative) --------
__global__ void k_thresh() {
    __shared__ unsigned int ps[1024];
    __shared__ unsigned int fb[128];
    __shared__ int gsel;
    __shared__ unsigned int exclv;
    int img = blockIdx.x, t = threadIdx.x;
    ps[t] = 0;
    __syncthreads();
    const uint4* h4 = (const uint4*)g_hist[img];
    #pragma unroll
    for (int k2 = 0; k2 < 32; k2++) {
        int q = t + k2 * 1024;            // uint4 index, 32768 total
        uint4 v = h4[q];
        int grp = 1023 - ((q * 4) >> 7);  // 128 bins per group, group 0 = top bins
        unsigned int s = v.x + v.y + v.z + v.w;
        if (s) atomicAdd(&ps[grp], s);
    }
    __syncthreads();
    for (int off = 1; off < 1024; off <<= 1) {
        unsigned int v = (t >= off) ? ps[t - off] : 0u;
        __syncthreads();
        ps[t] += v;
        __syncthreads();
    }
    if (ps[t] >= PRE_K && (t == 0 || ps[t - 1] < PRE_K)) {
        gsel = t;
        exclv = (t == 0) ? 0u : ps[t - 1];
    }
    __syncthreads();
    int g = gsel;
    int binHi = (1023 - g) * 128 + 127;
    if (t < 128) fb[t] = g_hist[img][binHi - t];   // descending within group
    __syncthreads();
    if (t == 0) {
        unsigned int cum = exclv;
        unsigned int th = 0;
        for (int m = 0; m < 128; m++) {
            cum += fb[m];
            if (cum >= PRE_K) { th = (unsigned int)(binHi - m); break; }
        }
        g_thresh[img] = th;
    }
}

// -------- stage 3: gather all candidates in bins >= threshold (float4) --------
__global__ void k_gather(const float4* __restrict__ obj4) {
    int img = blockIdx.y;
    int i = blockIdx.x * blockDim.x + threadIdx.x;
    if (i >= N_ANCH4) return;
    float4 v = obj4[(size_t)img * N_ANCH4 + i];
    unsigned int th = g_thresh[img];
    unsigned int ms[4] = {monof(v.x), monof(v.y), monof(v.z), monof(v.w)};
    #pragma unroll
    for (int q = 0; q < 4; q++) {
        if ((ms[q] >> 15) >= th) {
            unsigned int p = atomicAdd(&g_cnt[img], 1u);
            if (p < CAND_MAX) {
                unsigned int idx = (unsigned int)(i * 4 + q);
                g_cand[img][p] = ((unsigned long long)ms[q] << 32) | (~idx);
            }
        }
    }
}

// -------- stage 4: hybrid shared/shfl bitonic sort + box decode/clip --------
__global__ void k_sortdecode(const float4* __restrict__ anchors,
                             const float4* __restrict__ deltas) {
    __shared__ unsigned long long s[CAND_MAX];   // 32 KB
    int img = blockIdx.x;
    int tid = threadIdx.x;
    int lane = tid & 31, wid = tid >> 5;
    unsigned int cnt = g_cnt[img];
    int n = (cnt < CAND_MAX) ? (int)cnt : CAND_MAX;
    int S = (n <= 2048) ? 2048 : 4096;
    for (int i = tid; i < S; i += 1024)
        s[i] = (i < n) ? g_cand[img][i] : 0ull;
    __syncthreads();

    // register session: k = 2..32 entirely intra-warp (32-element chunks)
    int nChunks = S >> 5;
    for (int chunk = wid; chunk < nChunks; chunk += 32) {
        int e = (chunk << 5) + lane;
        unsigned long long v = s[e];
        #pragma unroll
        for (int k = 2; k <= 32; k <<= 1) {
            #pragma unroll
            for (int j = k >> 1; j > 0; j >>= 1) {
                unsigned long long p = __shfl_xor_sync(0xffffffffu, v, j);
                bool takeMax = (((e & j) == 0) == ((e & k) == 0));
                v = takeMax ? (v >= p ? v : p) : (v <= p ? v : p);
            }
        }
        s[e] = v;
    }
    __syncthreads();

    // k = 64..S: shared passes for j>=32, register shfl phase for j<=16
    for (int k = 64; k <= S; k <<= 1) {
        for (int j = k >> 1; j >= 32; j >>= 1) {
            for (int i = tid; i < S; i += 1024) {
                int ixj = i ^ j;
                if (ixj > i) {
                    unsigned long long a = s[i], b = s[ixj];
                    bool descSeg = (i & k) == 0;
                    if (descSeg ? (a < b) : (a > b)) { s[i] = b; s[ixj] = a; }
                }
            }
            __syncthreads();
        }
        for (int chunk = wid; chunk < nChunks; chunk += 32) {
            int e = (chunk << 5) + lane;
            unsigned long long v = s[e];
            #pragma unroll
            for (int j = 16; j > 0; j >>= 1) {
                unsigned long long p = __shfl_xor_sync(0xffffffffu, v, j);
                bool takeMax = (((e & j) == 0) == ((e & k) == 0));
                v = takeMax ? (v >= p ? v : p) : (v <= p ? v : p);
            }
            s[e] = v;
        }
        __syncthreads();
    }

    for (int t = tid; t < PRE_K; t += 1024) {
        unsigned long long key = s[t];
        unsigned int idx = ~(unsigned int)(key & 0xFFFFFFFFull);
        unsigned int m = (unsigned int)(key >> 32);
        float score = __uint_as_float((m & 0x80000000u) ? (m ^ 0x80000000u) : ~m);
        float4 a = anchors[idx];
        float4 d = deltas[(size_t)img * N_ANCH + idx];
        float w = a.z - a.x + 1.0f, h = a.w - a.y + 1.0f;
        float cx = a.x + 0.5f * w, cy = a.y + 0.5f * h;
        float dw = fminf(d.z, BBOX_CLIP), dh = fminf(d.w, BBOX_CLIP);
        float pcx = d.x * w + cx, pcy = d.y * h + cy;
        float pw = expf(dw) * w, ph = expf(dh) * h;
        float x1 = pcx - 0.5f * pw, y1 = pcy - 0.5f * ph;
        float x2 = pcx + 0.5f * pw - 1.0f, y2 = pcy + 0.5f * ph - 1.0f;
        x1 = fminf(fmaxf(x1, 0.0f), 1332.0f);
        y1 = fminf(fmaxf(y1, 0.0f), 799.0f);
        x2 = fminf(fmaxf(x2, 0.0f), 1332.0f);
        y2 = fminf(fmaxf(y2, 0.0f), 799.0f);
        g_box[img][t] = make_float4(x1, y1, x2, y2);
        g_score[img][t] = score;
        g_valid[img][t] = ((x2 - x1 + 1.0f) >= 0.0f && (y2 - y1 + 1.0f) >= 0.0f) ? 1 : 0;
    }
}

// -------- stage 5: IoU suppression, sparse nonzero-word list append --------
// triangular launch: 528 blocks/image, linear -> (rowB, colB) with colB >= rowB
__global__ void k_mask() {
    int lin = blockIdx.x, img = blockIdx.y;
    // invert lin = rowB*32 - rowB*(rowB-1)/2 + (colB - rowB)
    float lf = (float)lin;
    int rowB = (int)(32.5f - sqrtf(32.5f * 32.5f - 2.0f * lf - 0.001f));
    int base = rowB * 32 - (rowB * (rowB - 1)) / 2;
    while (base > lin) { rowB--; base = rowB * 32 - (rowB * (rowB - 1)) / 2; }
    while (rowB < 31) {
        int nb = (rowB + 1) * 32 - ((rowB + 1) * rowB) / 2;
        if (nb <= lin) { rowB++; base = nb; } else break;
    }
    int colB = rowB + (lin - base);

    __shared__ float4 cb[64];
    __shared__ float  ca[64];
    int t = threadIdx.x;
    int col0 = colB * 64;
    if (col0 + t < PRE_K) {
        float4 b = g_box[img][col0 + t];
        cb[t] = b;
        ca[t] = (b.z - b.x + 1.0f) * (b.w - b.y + 1.0f);
    }
    __syncthreads();
    int row = rowB * 64 + t;
    if (row >= PRE_K) return;
    float4 rb = g_box[img][row];
    float ra = (rb.z - rb.x + 1.0f) * (rb.w - rb.y + 1.0f);
    unsigned long long bits = 0;
    int cmax = min(64, PRE_K - col0);
    for (int c = 0; c < cmax; c++) {
        int col = col0 + c;
        if (col <= row) continue;
        float4 b = cb[c];
        float lx = fmaxf(rb.x, b.x), ly = fmaxf(rb.y, b.y);
        float rx = fminf(rb.z, b.z), ry = fminf(rb.w, b.w);
        float iw = fmaxf(rx - lx + 1.0f, 0.0f);
        float ih = fmaxf(ry - ly + 1.0f, 0.0f);
        float inter = iw * ih;
        if (inter > NMS_TH * (ra + ca[c] - inter)) bits |= 1ull << c;
    }
    if (bits) {
        unsigned int p = atomicAdd(&g_cnt2[img], 1u);
        if (p < LIST_MAX) {
            g_lkey[img][p] = (row << 5) | colB;
            g_lword[img][p] = bits;
        }
    }
}

// -------- stage 6: sparse greedy NMS (parallel sort) + stable partition + output --------
__global__ void k_nms_out(float* __restrict__ out) {
    int img = blockIdx.x, tid = threadIdx.x;
    __shared__ unsigned int       v32[64];
    __shared__ unsigned long long rem64[32];
    __shared__ unsigned long long keep64s[32];
    __shared__ int                skey[LIST_MAX];
    __shared__ unsigned long long sword[LIST_MAX];
    __shared__ int                wordPre[33];

    if (tid < 64) v32[tid] = 0;
    if (tid < 32) rem64[tid] = 0;
    __syncthreads();

    // validity bits via ballot (rows 0..1999)
    {
        int i = tid;
        unsigned char vv = (i < PRE_K) ? g_valid[img][i] : 0;
        unsigned int b = __ballot_sync(0xffffffffu, vv != 0);
        if ((tid & 31) == 0) v32[tid >> 5] = b;
        i = tid + 1024;
        vv = (i < PRE_K) ? g_valid[img][i] : 0;
        b = __ballot_sync(0xffffffffu, vv != 0);
        if ((tid & 31) == 0) v32[32 + (tid >> 5)] = b;
    }
    unsigned int c2 = g_cnt2[img];
    int n = (c2 < LIST_MAX) ? (int)c2 : LIST_MAX;
    int S2 = 32;
    while (S2 < n) S2 <<= 1;
    for (int e = tid; e < S2; e += 1024) {
        skey[e]  = (e < n) ? g_lkey[img][e] : 0x7FFFFFFF;
        sword[e] = (e < n) ? g_lword[img][e] : 0ull;
    }
    __syncthreads();

    // parallel bitonic sort ascending by key (keys unique), words move along
    if (n > 1) {
        for (int k = 2; k <= S2; k <<= 1) {
            for (int j = k >> 1; j > 0; j >>= 1) {
                for (int i = tid; i < S2; i += 1024) {
                    int ixj = i ^ j;
                    if (ixj > i) {
                        int a = skey[i], b = skey[ixj];
                        bool ascSeg = (i & k) == 0;
                        if (ascSeg ? (a > b) : (a < b)) {
                            skey[i] = b; skey[ixj] = a;
                            unsigned long long wa = sword[i];
                            sword[i] = sword[ixj]; sword[ixj] = wa;
                        }
                    }
                }
                __syncthreads();
            }
        }
    }

    if (tid == 0) {
        // exact greedy over sparse entries, rows ascending
        int e = 0;
        while (e < n) {
            int r = skey[e] >> 5;
            bool kp = ((v32[r >> 5] >> (r & 31)) & 1u) &&
                      !((rem64[r >> 6] >> (r & 63)) & 1ull);
            if (kp) {
                do { rem64[skey[e] & 31] |= sword[e]; e++; }
                while (e < n && (skey[e] >> 5) == r);
            } else {
                do { e++; } while (e < n && (skey[e] >> 5) == r);
            }
        }
    }
    __syncthreads();

    if (tid < 32) {
        unsigned long long vd = ((unsigned long long)v32[2 * tid]) |
                                (((unsigned long long)v32[2 * tid + 1]) << 32);
        unsigned long long kw = vd & ~rem64[tid];
        keep64s[tid] = kw;
        wordPre[tid] = __popcll(kw);
    }
    __syncthreads();
    if (tid == 0) {
        int c = 0;
        for (int q = 0; q < 32; q++) { int v = wordPre[q]; wordPre[q] = c; c += v; }
        wordPre[32] = c;
    }
    __syncthreads();

    int nk = wordPre[32];
    for (int i = tid; i < PRE_K; i += 1024) {
        int w = i >> 6, bit = i & 63;
        unsigned long long kw = keep64s[w];
        int before = wordPre[w] + __popcll(kw & ((1ull << bit) - 1ull));
        bool kept = (kw >> bit) & 1ull;
        int pos = kept ? before : nk + (i - before);
        if (pos < POST_K) {
            float4 bx = g_box[img][i];
            float sc = kept ? g_score[img][i] : -1e9f;
            float* o = out + ((size_t)img * POST_K + pos) * 5;
            o[0] = bx.x; o[1] = bx.y; o[2] = bx.z; o[3] = bx.w; o[4] = sc;
        }
    }
}

extern "C" void kernel_launch(void* const* d_in, const int* in_sizes, int n_in,
                              void* d_out, int out_size) {
    const float* anchors = (const float*)d_in[0];   // [250000,4]
    const float* obj     = (const float*)d_in[1];   // [8,250000]
    const float* deltas  = (const float*)d_in[2];   // [8,250000,4]
    float* out = (float*)d_out;                     // [8,1000,5]
    (void)in_sizes; (void)n_in; (void)out_size;

    void *hp, *cp, *c2p;
    cudaGetSymbolAddress(&hp, g_hist);
    cudaGetSymbolAddress(&cp, g_cnt);
    cudaGetSymbolAddress(&c2p, g_cnt2);
    cudaMemsetAsync(hp, 0, sizeof(unsigned int) * N_IMG * NBINS, 0);
    cudaMemsetAsync(cp, 0, sizeof(unsigned int) * N_IMG, 0);
    cudaMemsetAsync(c2p, 0, sizeof(unsigned int) * N_IMG, 0);

    dim3 gh((N_ANCH4 + 255) / 256, N_IMG);
    k_hist<<<gh, 256>>>((const float4*)obj);
    k_thresh<<<N_IMG, 1024>>>();
    k_gather<<<gh, 256>>>((const float4*)obj);
    k_sortdecode<<<N_IMG, 1024>>>((const float4*)anchors, (const float4*)deltas);
    k_mask<<<dim3(528, N_IMG), 64>>>();
    k_nms_out<<<N_IMG, 1024>>>(out);
}

// round 7
// speedup vs baseline: 4.8735x; 1.0048x over previous
#include <cuda_runtime.h>
#include <cuda_bf16.h>

#define N_IMG   8
#define N_ANCH  250000      // divisible by 4 -> 62500 float4 per image
#define N_ANCH4 62500
#define PRE_K   2000
#define POST_K  1000
#define NBINS   131072      // 17-bit monotone-float histogram
#define CAND_MAX 4096
#define LIST_MAX 2048
#define NMS_TH  0.7f
#define BBOX_CLIP 4.135166556742356f

// -------- persistent device scratch (no allocs allowed) --------
// Invariant: every kernel_launch leaves g_hist/g_cnt/g_cnt2 zeroed for the next replay.
__device__ unsigned int       g_hist[N_IMG][NBINS];     // 4 MB
__device__ unsigned int       g_thresh[N_IMG];
__device__ unsigned int       g_cnt[N_IMG];
__device__ unsigned long long g_cand[N_IMG][CAND_MAX];
__device__ float4             g_box[N_IMG][PRE_K];
__device__ float              g_score[N_IMG][PRE_K];
__device__ unsigned char      g_valid[N_IMG][PRE_K];
__device__ unsigned int       g_cnt2[N_IMG];
__device__ int                g_lkey[N_IMG][LIST_MAX];
__device__ unsigned long long g_lword[N_IMG][LIST_MAX];

__device__ __forceinline__ unsigned int monof(float f) {
    unsigned int u = __float_as_uint(f);
    return (u & 0x80000000u) ? ~u : (u | 0x80000000u);
}
__device__ __forceinline__ unsigned long long umax64(unsigned long long a, unsigned long long b) { return a > b ? a : b; }
__device__ __forceinline__ unsigned long long umin64(unsigned long long a, unsigned long long b) { return a < b ? a : b; }

// -------- stage 1: histogram over top 17 bits of monotone key (float4) --------
__global__ void k_hist(const float4* __restrict__ obj4) {
    int img = blockIdx.y;
    int i = blockIdx.x * blockDim.x + threadIdx.x;
    if (i < N_ANCH4) {
        float4 v = obj4[(size_t)img * N_ANCH4 + i];
        atomicAdd(&g_hist[img][monof(v.x) >> 15], 1u);
        atomicAdd(&g_hist[img][monof(v.y) >> 15], 1u);
        atomicAdd(&g_hist[img][monof(v.z) >> 15], 1u);
        atomicAdd(&g_hist[img][monof(v.w) >> 15], 1u);
    }
}

// -------- stage 2: threshold bin + self-clean (zero hist & g_cnt for next stage/replay) --------
__global__ void k_thresh() {
    __shared__ unsigned int ps[1024];
    __shared__ unsigned int fb[128];
    __shared__ int gsel;
    __shared__ unsigned int exclv;
    int img = blockIdx.x, t = threadIdx.x;
    ps[t] = 0;
    if (t == 0) g_cnt[img] = 0;          // reset candidate counter before k_gather
    __syncthreads();
    const uint4* h4 = (const uint4*)g_hist[img];
    #pragma unroll
    for (int k2 = 0; k2 < 32; k2++) {
        int q = t + k2 * 1024;            // uint4 index, 32768 total
        uint4 v = h4[q];
        int grp = 1023 - ((q * 4) >> 7);  // 128 bins per group, group 0 = top bins
        unsigned int s = v.x + v.y + v.z + v.w;
        if (s) atomicAdd(&ps[grp], s);
    }
    __syncthreads();
    for (int off = 1; off < 1024; off <<= 1) {
        unsigned int v = (t >= off) ? ps[t - off] : 0u;
        __syncthreads();
        ps[t] += v;
        __syncthreads();
    }
    if (ps[t] >= PRE_K && (t == 0 || ps[t - 1] < PRE_K)) {
        gsel = t;
        exclv = (t == 0) ? 0u : ps[t - 1];
    }
    __syncthreads();
    int g = gsel;
    int binHi = (1023 - g) * 128 + 127;
    if (t < 128) fb[t] = g_hist[img][binHi - t];   // descending within group
    __syncthreads();
    if (t == 0) {
        unsigned int cum = exclv;
        unsigned int th = 0;
        for (int m = 0; m < 128; m++) {
            cum += fb[m];
            if (cum >= PRE_K) { th = (unsigned int)(binHi - m); break; }
        }
        g_thresh[img] = th;
    }
    // self-clean: zero this image's histogram (replaces a cudaMemsetAsync node)
    uint4* h4w = (uint4*)g_hist[img];
    uint4 z = make_uint4(0u, 0u, 0u, 0u);
    #pragma unroll
    for (int k2 = 0; k2 < 32; k2++)
        h4w[t + k2 * 1024] = z;
}

// -------- stage 3: gather all candidates in bins >= threshold (float4) --------
__global__ void k_gather(const float4* __restrict__ obj4) {
    int img = blockIdx.y;
    int i = blockIdx.x * blockDim.x + threadIdx.x;
    if (i >= N_ANCH4) return;
    float4 v = obj4[(size_t)img * N_ANCH4 + i];
    unsigned int th = g_thresh[img];
    unsigned int ms[4] = {monof(v.x), monof(v.y), monof(v.z), monof(v.w)};
    #pragma unroll
    for (int q = 0; q < 4; q++) {
        if ((ms[q] >> 15) >= th) {
            unsigned int p = atomicAdd(&g_cnt[img], 1u);
            if (p < CAND_MAX) {
                unsigned int idx = (unsigned int)(i * 4 + q);
                g_cand[img][p] = ((unsigned long long)ms[q] << 32) | (~idx);
            }
        }
    }
}

// -------- stage 4: paired-element hybrid bitonic sort + box decode/clip --------
__global__ void k_sortdecode(const float4* __restrict__ anchors,
                             const float4* __restrict__ deltas) {
    __shared__ unsigned long long s[CAND_MAX];   // 32 KB
    int img = blockIdx.x;
    int tid = threadIdx.x;
    int lane = tid & 31, wid = tid >> 5;
    if (tid == 0) g_cnt2[img] = 0;               // reset sparse-list counter before k_mask
    unsigned int cnt = g_cnt[img];
    int n = (cnt < CAND_MAX) ? (int)cnt : CAND_MAX;
    int S = (n <= 2048) ? 2048 : 4096;
    for (int i = tid; i < S; i += 1024)
        s[i] = (i < n) ? g_cand[img][i] : 0ull;
    __syncthreads();

    int nChunks64 = S >> 6;                      // 64-element chunks
    // initial register session: k = 2..64 fully in registers (2 elems/thread)
    for (int chunk = wid; chunk < nChunks64; chunk += 32) {
        int e0 = (chunk << 6) + lane;
        int e1 = e0 + 32;
        unsigned long long v0 = s[e0], v1 = s[e1];
        #pragma unroll
        for (int k = 2; k <= 32; k <<= 1) {
            #pragma unroll
            for (int j = k >> 1; j > 0; j >>= 1) {
                unsigned long long p0 = __shfl_xor_sync(0xffffffffu, v0, j);
                unsigned long long p1 = __shfl_xor_sync(0xffffffffu, v1, j);
                bool tm0 = (((e0 & j) == 0) == ((e0 & k) == 0));
                bool tm1 = (((e1 & j) == 0) == ((e1 & k) == 0));
                v0 = tm0 ? umax64(v0, p0) : umin64(v0, p0);
                v1 = tm1 ? umax64(v1, p1) : umin64(v1, p1);
            }
        }
        {   // k = 64: j=32 is the local pair, then j=16..1 shfl
            bool tm0 = ((e0 & 64) == 0);
            unsigned long long mx = umax64(v0, v1), mn = umin64(v0, v1);
            v0 = tm0 ? mx : mn;
            v1 = tm0 ? mn : mx;
            #pragma unroll
            for (int j = 16; j > 0; j >>= 1) {
                unsigned long long p0 = __shfl_xor_sync(0xffffffffu, v0, j);
                unsigned long long p1 = __shfl_xor_sync(0xffffffffu, v1, j);
                bool t0 = (((e0 & j) == 0) == ((e0 & 64) == 0));
                bool t1 = (((e1 & j) == 0) == ((e1 & 64) == 0));
                v0 = t0 ? umax64(v0, p0) : umin64(v0, p0);
                v1 = t1 ? umax64(v1, p1) : umin64(v1, p1);
            }
        }
        s[e0] = v0; s[e1] = v1;
    }
    __syncthreads();

    // k = 128..S: shared passes for j>=64, register session for j<=32
    for (int k = 128; k <= S; k <<= 1) {
        for (int j = k >> 1; j >= 64; j >>= 1) {
            for (int i = tid; i < S; i += 1024) {
                int ixj = i ^ j;
                if (ixj > i) {
                    unsigned long long a = s[i], b = s[ixj];
                    bool descSeg = (i & k) == 0;
                    if (descSeg ? (a < b) : (a > b)) { s[i] = b; s[ixj] = a; }
                }
            }
            __syncthreads();
        }
        for (int chunk = wid; chunk < nChunks64; chunk += 32) {
            int e0 = (chunk << 6) + lane;
            int e1 = e0 + 32;
            unsigned long long v0 = s[e0], v1 = s[e1];
            bool tm0 = ((e0 & k) == 0);          // j=32 local pair
            unsigned long long mx = umax64(v0, v1), mn = umin64(v0, v1);
            v0 = tm0 ? mx : mn;
            v1 = tm0 ? mn : mx;
            #pragma unroll
            for (int j = 16; j > 0; j >>= 1) {
                unsigned long long p0 = __shfl_xor_sync(0xffffffffu, v0, j);
                unsigned long long p1 = __shfl_xor_sync(0xffffffffu, v1, j);
                bool t0 = (((e0 & j) == 0) == ((e0 & k) == 0));
                bool t1 = (((e1 & j) == 0) == ((e1 & k) == 0));
                v0 = t0 ? umax64(v0, p0) : umin64(v0, p0);
                v1 = t1 ? umax64(v1, p1) : umin64(v1, p1);
            }
            s[e0] = v0; s[e1] = v1;
        }
        __syncthreads();
    }

    for (int t = tid; t < PRE_K; t += 1024) {
        unsigned long long key = s[t];
        unsigned int idx = ~(unsigned int)(key & 0xFFFFFFFFull);
        unsigned int m = (unsigned int)(key >> 32);
        float score = __uint_as_float((m & 0x80000000u) ? (m ^ 0x80000000u) : ~m);
        float4 a = anchors[idx];
        float4 d = deltas[(size_t)img * N_ANCH + idx];
        float w = a.z - a.x + 1.0f, h = a.w - a.y + 1.0f;
        float cx = a.x + 0.5f * w, cy = a.y + 0.5f * h;
        float dw = fminf(d.z, BBOX_CLIP), dh = fminf(d.w, BBOX_CLIP);
        float pcx = d.x * w + cx, pcy = d.y * h + cy;
        float pw = expf(dw) * w, ph = expf(dh) * h;
        float x1 = pcx - 0.5f * pw, y1 = pcy - 0.5f * ph;
        float x2 = pcx + 0.5f * pw - 1.0f, y2 = pcy + 0.5f * ph - 1.0f;
        x1 = fminf(fmaxf(x1, 0.0f), 1332.0f);
        y1 = fminf(fmaxf(y1, 0.0f), 799.0f);
        x2 = fminf(fmaxf(x2, 0.0f), 1332.0f);
        y2 = fminf(fmaxf(y2, 0.0f), 799.0f);
        g_box[img][t] = make_float4(x1, y1, x2, y2);
        g_score[img][t] = score;
        g_valid[img][t] = ((x2 - x1 + 1.0f) >= 0.0f && (y2 - y1 + 1.0f) >= 0.0f) ? 1 : 0;
    }
}

// -------- stage 5: IoU suppression, sparse nonzero-word list append --------
// 4 triangle tiles per 256-thread block; 132 blocks per image
__global__ void k_mask() {
    int img = blockIdx.y;
    int sub = threadIdx.x >> 6;
    int t = threadIdx.x & 63;
    int lin = blockIdx.x * 4 + sub;
    // invert lin = rowB*32 - rowB*(rowB-1)/2 + (colB - rowB)
    float lf = (float)lin;
    int rowB = (int)(32.5f - sqrtf(32.5f * 32.5f - 2.0f * lf - 0.001f));
    int base = rowB * 32 - (rowB * (rowB - 1)) / 2;
    while (base > lin) { rowB--; base = rowB * 32 - (rowB * (rowB - 1)) / 2; }
    while (rowB < 31) {
        int nb = (rowB + 1) * 32 - ((rowB + 1) * rowB) / 2;
        if (nb <= lin) { rowB++; base = nb; } else break;
    }
    int colB = rowB + (lin - base);

    __shared__ float4 cb[4][64];
    __shared__ float  ca[4][64];
    int col0 = colB * 64;
    if (col0 + t < PRE_K) {
        float4 b = g_box[img][col0 + t];
        cb[sub][t] = b;
        ca[sub][t] = (b.z - b.x + 1.0f) * (b.w - b.y + 1.0f);
    }
    __syncthreads();
    int row = rowB * 64 + t;
    if (row >= PRE_K) return;
    float4 rb = g_box[img][row];
    float ra = (rb.z - rb.x + 1.0f) * (rb.w - rb.y + 1.0f);
    unsigned long long bits = 0;
    int cmax = min(64, PRE_K - col0);
    for (int c = 0; c < cmax; c++) {
        int col = col0 + c;
        if (col <= row) continue;
        float4 b = cb[sub][c];
        float lx = fmaxf(rb.x, b.x), ly = fmaxf(rb.y, b.y);
        float rx = fminf(rb.z, b.z), ry = fminf(rb.w, b.w);
        float iw = fmaxf(rx - lx + 1.0f, 0.0f);
        float ih = fmaxf(ry - ly + 1.0f, 0.0f);
        float inter = iw * ih;
        if (inter > NMS_TH * (ra + ca[sub][c] - inter)) bits |= 1ull << c;
    }
    if (bits) {
        unsigned int p = atomicAdd(&g_cnt2[img], 1u);
        if (p < LIST_MAX) {
            g_lkey[img][p] = (row << 5) | colB;
            g_lword[img][p] = bits;
        }
    }
}

// -------- stage 6: sparse greedy NMS (parallel sort) + stable partition + output --------
__global__ void k_nms_out(float* __restrict__ out) {
    int img = blockIdx.x, tid = threadIdx.x;
    __shared__ unsigned int       v32[64];
    __shared__ unsigned long long rem64[32];
    __shared__ unsigned long long keep64s[32];
    __shared__ int                skey[LIST_MAX];
    __shared__ unsigned long long sword[LIST_MAX];
    __shared__ int                wordPre[33];

    if (tid < 64) v32[tid] = 0;
    if (tid < 32) rem64[tid] = 0;
    __syncthreads();

    // validity bits via ballot (rows 0..1999)
    {
        int i = tid;
        unsigned char vv = (i < PRE_K) ? g_valid[img][i] : 0;
        unsigned int b = __ballot_sync(0xffffffffu, vv != 0);
        if ((tid & 31) == 0) v32[tid >> 5] = b;
        i = tid + 1024;
        vv = (i < PRE_K) ? g_valid[img][i] : 0;
        b = __ballot_sync(0xffffffffu, vv != 0);
        if ((tid & 31) == 0) v32[32 + (tid >> 5)] = b;
    }
    unsigned int c2 = g_cnt2[img];
    int n = (c2 < LIST_MAX) ? (int)c2 : LIST_MAX;
    int S2 = 32;
    while (S2 < n) S2 <<= 1;
    for (int e = tid; e < S2; e += 1024) {
        skey[e]  = (e < n) ? g_lkey[img][e] : 0x7FFFFFFF;
        sword[e] = (e < n) ? g_lword[img][e] : 0ull;
    }
    __syncthreads();

    // parallel bitonic sort ascending by key (keys unique), words move along
    if (n > 1) {
        for (int k = 2; k <= S2; k <<= 1) {
            for (int j = k >> 1; j > 0; j >>= 1) {
                for (int i = tid; i < S2; i += 1024) {
                    int ixj = i ^ j;
                    if (ixj > i) {
                        int a = skey[i], b = skey[ixj];
                        bool ascSeg = (i & k) == 0;
                        if (ascSeg ? (a > b) : (a < b)) {
                            skey[i] = b; skey[ixj] = a;
                            unsigned long long wa = sword[i];
                            sword[i] = sword[ixj]; sword[ixj] = wa;
                        }
                    }
                }
                __syncthreads();
            }
        }
    }

    if (tid == 0) {
        // exact greedy over sparse entries, rows ascending
        int e = 0;
        while (e < n) {
            int r = skey[e] >> 5;
            bool kp = ((v32[r >> 5] >> (r & 31)) & 1u) &&
                      !((rem64[r >> 6] >> (r & 63)) & 1ull);
            if (kp) {
                do { rem64[skey[e] & 31] |= sword[e]; e++; }
                while (e < n && (skey[e] >> 5) == r);
            } else {
                do { e++; } while (e < n && (skey[e] >> 5) == r);
            }
        }
    }
    __syncthreads();

    if (tid < 32) {
        unsigned long long vd = ((unsigned long long)v32[2 * tid]) |
                                (((unsigned long long)v32[2 * tid + 1]) << 32);
        unsigned long long kw = vd & ~rem64[tid];
        keep64s[tid] = kw;
        wordPre[tid] = __popcll(kw);
    }
    __syncthreads();
    if (tid == 0) {
        int c = 0;
        for (int q = 0; q < 32; q++) { int v = wordPre[q]; wordPre[q] = c; c += v; }
        wordPre[32] = c;
    }
    __syncthreads();

    int nk = wordPre[32];
    for (int i = tid; i < PRE_K; i += 1024) {
        int w = i >> 6, bit = i & 63;
        unsigned long long kw = keep64s[w];
        int before = wordPre[w] + __popcll(kw & ((1ull << bit) - 1ull));
        bool kept = (kw >> bit) & 1ull;
        int pos = kept ? before : nk + (i - before);
        if (pos < POST_K) {
            float4 bx = g_box[img][i];
            float sc = kept ? g_score[img][i] : -1e9f;
            float* o = out + ((size_t)img * POST_K + pos) * 5;
            o[0] = bx.x; o[1] = bx.y; o[2] = bx.z; o[3] = bx.w; o[4] = sc;
        }
    }
}

extern "C" void kernel_launch(void* const* d_in, const int* in_sizes, int n_in,
                              void* d_out, int out_size) {
    const float* anchors = (const float*)d_in[0];   // [250000,4]
    const float* obj     = (const float*)d_in[1];   // [8,250000]
    const float* deltas  = (const float*)d_in[2];   // [8,250000,4]
    float* out = (float*)d_out;                     // [8,1000,5]
    (void)in_sizes; (void)n_in; (void)out_size;

    dim3 gh((N_ANCH4 + 255) / 256, N_IMG);
    k_hist<<<gh, 256>>>((const float4*)obj);
    k_thresh<<<N_IMG, 1024>>>();
    k_gather<<<gh, 256>>>((const float4*)obj);
    k_sortdecode<<<N_IMG, 1024>>>((const float4*)anchors, (const float4*)deltas);
    k_mask<<<dim3(132, N_IMG), 256>>>();
    k_nms_out<<<N_IMG, 1024>>>(out);
}